// round 12
// baseline (speedup 1.0000x reference)
#include <cuda_runtime.h>
#include <math.h>
#include <stdint.h>

// Problem constants
#define B_   8
#define P_   16384
#define M_   16
#define CI_  16
#define CO_  32
#define W_   17
#define OSTRIDE 288       // floats per output row in Wf (17 w-slots + residual col)
#define WWM  24           // per-m stride in ww_s (2 wp-halves of 12)
#define WARP_SM 400       // per-warp smem floats: ww 16*24=384 + nb 16

typedef unsigned long long ull;

// packed f32x2 (SASS FFMA2) — only reachable via PTX
#define FMA_F32X2(d, a, b, c) \
    asm("fma.rn.f32x2 %0, %1, %2, %3;" : "=l"(d) : "l"(a), "l"(b), "l"(c))
#define PACK_REPL_F32X2(out, s) \
    asm("mov.b64 %0, {%1, %1};" : "=l"(out) : "r"(s))
#define UNPACK_F32X2(lo, hi, in) \
    asm("mov.b64 {%0, %1}, %2;" : "=r"(lo), "=r"(hi) : "l"(in))

// smem (floats): Wf [32][288] = 9216 ; per-warp (4): ww[16][24] + nb[16] = 400
// total = 9216 + 1600 = 10816 floats = 43264 bytes

__global__ void __launch_bounds__(128, 4)
fused_conv_kernel(const float* __restrict__ in_pc,
                  const float* __restrict__ weights,
                  const float* __restrict__ bias,
                  const float* __restrict__ w_weights,
                  const int*   __restrict__ neighbor_id,
                  float*       __restrict__ out)
{
    constexpr float SQ_CONV = 0.70710678118654752440f;

    extern __shared__ float sm[];
    float* Wf = sm;                                   // [32][288]

    const int tid  = threadIdx.x;
    const int warp = tid >> 5;
    const int lane = tid & 31;

    float* ww_s = sm + 32 * OSTRIDE + warp * WARP_SM; // [16][24]
    int*   nb_s = (int*)(ww_s + 384);                 // [16]

    // ---- stage weights: Wf[o][w*16+i] (col 272.. zeroed) ----
    for (int idx = tid; idx < W_ * 512; idx += 128) {
        int w   = idx >> 9;
        int rem = idx & 511;
        int o   = rem >> 4;
        int i   = rem & 15;
        Wf[o * OSTRIDE + w * 16 + i] = weights[idx];
    }
    for (int idx = tid; idx < 512; idx += 128) {
        int o = idx >> 4, i = idx & 15;
        Wf[o * OSTRIDE + 272 + i] = 0.0f;
    }

    const int p = blockIdx.x * 4 + warp;

    // ---- per-warp staging: neighbor ids, masked ww (parity-split layout) ----
    if (lane < 16) {
        nb_s[lane] = neighbor_id[p * M_ + lane];
        ww_s[lane * WWM + 12 + 8] = 0.0f;     // wp1 slot8 = 0 (unused slot)
    }
    __syncwarp();
    for (int idx = lane; idx < 272; idx += 32) {
        int m = idx / 17;
        int w = idx - m * 17;
        float v = w_weights[(size_t)p * 272 + idx];
        // slot: wp = w&1 ; s = w>>1  (w=16 -> wp0 s8)
        ww_s[m * WWM + (w & 1) * 12 + (w >> 1)] = (nb_s[m] == P_) ? 0.0f : v;
    }
    __syncthreads();

    // lane bits: bg = bit4 ; wp = bit3 ; ih (channel pair) = bits 0-2
    // XOR-permuted slot ownership: oL = (lane>>2)&3, jL = lane&3.
    const int bg = (lane >> 4) & 1;
    const int wp = (lane >> 3) & 1;
    const int ih = lane & 7;
    const int oL = (lane >> 2) & 3;
    const int jL = lane & 3;

    // physical batch slot sj holds batch b = bg + 2*(sj ^ jL)
    const float* xb[4];
    #pragma unroll
    for (int sj = 0; sj < 4; sj++)
        xb[sj] = in_pc + (size_t)(bg + 2 * (sj ^ jL)) * P_ * CI_ + 2 * ih;

    // gacc2[s][sj]: packed ch-pair accumulators. s=0..7: w=2s+wp ;
    // s=8: wp0 -> w=16 conv ; wp1 -> zero (ww slot8 = 0)
    ull gacc2[9][4];
    #pragma unroll
    for (int s = 0; s < 9; s++) {
        gacc2[s][0] = 0ull; gacc2[s][1] = 0ull;
        gacc2[s][2] = 0ull; gacc2[s][3] = 0ull;
    }

    // ---- stage A ----
    const float* wwp = ww_s + wp * 12;
    #pragma unroll 4
    for (int m = 0; m < M_; m++) {
        int nb  = nb_s[m];
        int nbc = (nb == P_) ? 0 : nb;          // ww zeroed for pad
        size_t xo = (size_t)nbc * CI_;
        ull x0 = *(const ull*)(xb[0] + xo);
        ull x1 = *(const ull*)(xb[1] + xo);
        ull x2 = *(const ull*)(xb[2] + xo);
        ull x3 = *(const ull*)(xb[3] + xo);
        const float* wm = wwp + m * WWM;
        float4 fA = *(const float4*)(wm);
        float4 fB = *(const float4*)(wm + 4);
        float  f8 = wm[8];
        float fs[9] = {fA.x, fA.y, fA.z, fA.w, fB.x, fB.y, fB.z, fB.w, f8};
        #pragma unroll
        for (int s = 0; s < 9; s++) {
            ull f2;
            uint32_t fb = __float_as_uint(fs[s]);
            PACK_REPL_F32X2(f2, fb);
            FMA_F32X2(gacc2[s][0], f2, x0, gacc2[s][0]);
            FMA_F32X2(gacc2[s][1], f2, x1, gacc2[s][1]);
            FMA_F32X2(gacc2[s][2], f2, x2, gacc2[s][2]);
            FMA_F32X2(gacc2[s][3], f2, x3, gacc2[s][3]);
        }
    }

    // ---- stage B: XOR-permuted slots; each Wf LDS.64 feeds 4 FFMA2 ----
    const float* wfb = Wf + wp * 16 + 2 * ih;
    const float* biasp = bias + (size_t)p * CO_;
    float* outb = out + ((size_t)(bg + 2 * jL) * P_ + p) * CO_;

    #pragma unroll 2
    for (int og = 0; og < 8; og++) {
        float av[4][4];

        #pragma unroll
        for (int so = 0; so < 4; so++) {
            const float* wfoo = wfb + (size_t)(og * 4 + (so ^ oL)) * OSTRIDE;

            ull acc2[4] = {0ull, 0ull, 0ull, 0ull};
            #pragma unroll
            for (int s = 0; s < 8; s++) {
                ull wv = *(const ull*)(wfoo + s * 32);
                FMA_F32X2(acc2[0], wv, gacc2[s][0], acc2[0]);
                FMA_F32X2(acc2[1], wv, gacc2[s][1], acc2[1]);
                FMA_F32X2(acc2[2], wv, gacc2[s][2], acc2[2]);
                FMA_F32X2(acc2[3], wv, gacc2[s][3], acc2[3]);
            }
            ull wv8 = *(const ull*)(wfoo + 256);
            FMA_F32X2(acc2[0], wv8, gacc2[8][0], acc2[0]);
            FMA_F32X2(acc2[1], wv8, gacc2[8][1], acc2[1]);
            FMA_F32X2(acc2[2], wv8, gacc2[8][2], acc2[2]);
            FMA_F32X2(acc2[3], wv8, gacc2[8][3], acc2[3]);

            #pragma unroll
            for (int sj = 0; sj < 4; sj++) {
                uint32_t lo, hi;
                UNPACK_F32X2(lo, hi, acc2[sj]);
                av[so][sj] = __uint_as_float(lo) + __uint_as_float(hi);
            }
        }

        // ---- select-free reduce-scatter (recursive halving, XOR slots) ----
        #pragma unroll
        for (int so = 0; so < 2; so++) {
            #pragma unroll
            for (int sj = 0; sj < 4; sj++)
                av[so][sj] += __shfl_xor_sync(0xffffffffu, av[so + 2][sj], 8);
        }
        #pragma unroll
        for (int sj = 0; sj < 4; sj++)
            av[0][sj] += __shfl_xor_sync(0xffffffffu, av[1][sj], 4);
        #pragma unroll
        for (int sj = 0; sj < 2; sj++)
            av[0][sj] += __shfl_xor_sync(0xffffffffu, av[0][sj + 2], 2);
        av[0][0] += __shfl_xor_sync(0xffffffffu, av[0][1], 1);

        // ---- epilogue: lane owns (o = og*4 + oL, b = bg + 2*jL) ----
        const int o = og * 4 + oL;
        float c = av[0][0] + biasp[o];
        float e = (c > 0.0f) ? c : expm1f(c);
        outb[o] = e * SQ_CONV;            // residual added by kernel 2
    }
}

// ---- kernel 2: out += SQ_RES * (wres[o,:] . x[b,p,:]) ----
// One warp = 4 points, fully unrolled, all loads batch-issued (max MLP).
// 131072 points / 4 per warp / 4 warps per block = 8192 blocks.
__global__ void __launch_bounds__(128, 8)
residual_kernel(const float* __restrict__ in_pc,
                const float* __restrict__ weight_res,
                float*       __restrict__ out)
{
    constexpr float SQ_RES = 0.70710678118654752440f;

    const int lane = threadIdx.x & 31;
    const int gw   = blockIdx.x * 4 + (threadIdx.x >> 5);
    const int base = gw * 4;   // 4 consecutive (b,p) points

    // wres row for this lane's o (4 LDG.128, L1/L2-cached across warps)
    float4 w0 = __ldg((const float4*)&weight_res[lane * 16]);
    float4 w1 = __ldg((const float4*)&weight_res[lane * 16 + 4]);
    float4 w2 = __ldg((const float4*)&weight_res[lane * 16 + 8]);
    float4 w3 = __ldg((const float4*)&weight_res[lane * 16 + 12]);

    // batch-issue all x loads (16 LDG.128, uniform per warp)
    float4 x[4][4];
    #pragma unroll
    for (int t = 0; t < 4; t++) {
        const float* xp = in_pc + (size_t)(base + t) * CI_;
        x[t][0] = __ldg((const float4*)(xp));
        x[t][1] = __ldg((const float4*)(xp + 4));
        x[t][2] = __ldg((const float4*)(xp + 8));
        x[t][3] = __ldg((const float4*)(xp + 12));
    }
    // batch-issue all out loads (4 LDG.32, coalesced 128B/warp)
    float ov[4];
    #pragma unroll
    for (int t = 0; t < 4; t++)
        ov[t] = out[(size_t)(base + t) * CO_ + lane];

    #pragma unroll
    for (int t = 0; t < 4; t++) {
        float r = w0.x*x[t][0].x + w0.y*x[t][0].y + w0.z*x[t][0].z + w0.w*x[t][0].w
                + w1.x*x[t][1].x + w1.y*x[t][1].y + w1.z*x[t][1].z + w1.w*x[t][1].w
                + w2.x*x[t][2].x + w2.y*x[t][2].y + w2.z*x[t][2].z + w2.w*x[t][2].w
                + w3.x*x[t][3].x + w3.y*x[t][3].y + w3.z*x[t][3].z + w3.w*x[t][3].w;
        out[(size_t)(base + t) * CO_ + lane] = ov[t] + r * SQ_RES;
    }
}

extern "C" void kernel_launch(void* const* d_in, const int* in_sizes, int n_in,
                              void* d_out, int out_size)
{
    const float* in_pc       = nullptr;
    const float* weights     = nullptr;
    const float* bias        = nullptr;
    const float* w_weights   = nullptr;
    const float* weight_res  = nullptr;
    const int*   neighbor_id = nullptr;

    for (int i = 0; i < n_in; i++) {
        switch (in_sizes[i]) {
            case 2097152: in_pc       = (const float*)d_in[i]; break; // (8,16384,16)
            case 8704:    weights     = (const float*)d_in[i]; break; // (17,512)
            case 524288:  bias        = (const float*)d_in[i]; break; // (16384,32)
            case 4456448: w_weights   = (const float*)d_in[i]; break; // (16384,16,17)
            case 512:     weight_res  = (const float*)d_in[i]; break; // (32,16)
            case 262144:  neighbor_id = (const int*)d_in[i];   break; // (16384,16)
            default: break;
        }
    }

    const int smem_bytes = (32 * OSTRIDE + 4 * WARP_SM) * 4; // 43264
    cudaFuncSetAttribute(fused_conv_kernel,
                         cudaFuncAttributeMaxDynamicSharedMemorySize, smem_bytes);

    fused_conv_kernel<<<P_ / 4, 128, smem_bytes>>>(
        in_pc, weights, bias, w_weights, neighbor_id, (float*)d_out);

    // 131072 points / 4 per warp / 4 warps per block = 8192 blocks
    residual_kernel<<<8192, 128>>>(in_pc, weight_res, (float*)d_out);
}

// round 13
// speedup vs baseline: 1.0636x; 1.0636x over previous
#include <cuda_runtime.h>
#include <math.h>
#include <stdint.h>

// Problem constants
#define B_   8
#define P_   16384
#define M_   16
#define CI_  16
#define CO_  32
#define W_   17
#define OSTRIDE 288       // floats per output row in Wf (17 w-slots + residual col)
#define WWM  24           // per-m stride in ww_s (2 wp-halves of 12)
#define WARP_SM 400       // per-warp smem floats: ww 16*24=384 + nb 16

typedef unsigned long long ull;

// packed f32x2 (SASS FFMA2) — only reachable via PTX
#define FMA_F32X2(d, a, b, c) \
    asm("fma.rn.f32x2 %0, %1, %2, %3;" : "=l"(d) : "l"(a), "l"(b), "l"(c))
#define MUL_F32X2(d, a, b) \
    asm("mul.rn.f32x2 %0, %1, %2;" : "=l"(d) : "l"(a), "l"(b))
#define PACK_REPL_F32X2(out, s) \
    asm("mov.b64 %0, {%1, %1};" : "=l"(out) : "r"(s))
#define UNPACK_F32X2(lo, hi, in) \
    asm("mov.b64 {%0, %1}, %2;" : "=r"(lo), "=r"(hi) : "l"(in))

// smem (floats): Wf [32][288] = 9216 ; per-warp (4): ww[16][24] + nb[16] = 400
// total = 9216 + 1600 = 10816 floats = 43264 bytes

__global__ void __launch_bounds__(128, 4)
fused_conv_kernel(const float* __restrict__ in_pc,
                  const float* __restrict__ weights,
                  const float* __restrict__ bias,
                  const float* __restrict__ w_weights,
                  const float* __restrict__ weight_res,
                  const int*   __restrict__ neighbor_id,
                  float*       __restrict__ out)
{
    constexpr float SQ_CONV = 0.70710678118654752440f;
    constexpr float SQ_RES  = 0.70710678118654752440f;

    extern __shared__ float sm[];
    float* Wf = sm;                                   // [32][288]

    const int tid  = threadIdx.x;
    const int warp = tid >> 5;
    const int lane = tid & 31;

    float* ww_s = sm + 32 * OSTRIDE + warp * WARP_SM; // [16][24]
    int*   nb_s = (int*)(ww_s + 384);                 // [16]

    // ---- stage weights: Wf[o][w*16+i]; col 272..287 = weight_res[o][:] ----
    for (int idx = tid; idx < W_ * 512; idx += 128) {
        int w   = idx >> 9;
        int rem = idx & 511;
        int o   = rem >> 4;
        int i   = rem & 15;
        Wf[o * OSTRIDE + w * 16 + i] = weights[idx];
    }
    for (int idx = tid; idx < 512; idx += 128) {
        int o = idx >> 4, i = idx & 15;
        Wf[o * OSTRIDE + 272 + i] = weight_res[idx];
    }

    const int p = blockIdx.x * 4 + warp;

    // ---- per-warp staging: neighbor ids, masked ww (parity-split layout) ----
    if (lane < 16) {
        nb_s[lane] = neighbor_id[p * M_ + lane];
        ww_s[lane * WWM + 12 + 8] = 0.0f;     // wp1 slot8 = 0 (keeps gacc2[8]=0)
    }
    __syncwarp();
    for (int idx = lane; idx < 272; idx += 32) {
        int m = idx / 17;
        int w = idx - m * 17;
        float v = w_weights[(size_t)p * 272 + idx];
        // slot: wp = w&1 ; s = w>>1  (w=16 -> wp0 s8)
        ww_s[m * WWM + (w & 1) * 12 + (w >> 1)] = (nb_s[m] == P_) ? 0.0f : v;
    }
    __syncthreads();

    // lane bits: bg = bit4 ; wp = bit3 ; ih (channel pair) = bits 0-2
    // XOR-permuted slot ownership: oL = (lane>>2)&3 (= wp*2 + h2), jL = lane&3.
    const int bg = (lane >> 4) & 1;
    const int wp = (lane >> 3) & 1;
    const int ih = lane & 7;
    const int oL = (lane >> 2) & 3;
    const int jL = lane & 3;
    const int b_fin = bg + 2 * jL;

    // physical batch slot sj holds batch b = bg + 2*(sj ^ jL)
    const float* xb[4];
    #pragma unroll
    for (int sj = 0; sj < 4; sj++)
        xb[sj] = in_pc + (size_t)(bg + 2 * (sj ^ jL)) * P_ * CI_ + 2 * ih;

    // residual input: this lane's channel-QUARTER (q = oL) of its own (b_fin, p)
    ull xq0, xq1;
    {
        const ull* xqp = (const ull*)(in_pc + ((size_t)b_fin * P_ + p) * CI_ + oL * 4);
        xq0 = xqp[0];
        xq1 = xqp[1];
    }

    // gacc2[s][sj]: packed ch-pair accumulators. s=0..7: w=2s+wp ;
    // s=8: wp0 -> w=16 conv ; wp1 -> zero (ww slot8 = 0)
    ull gacc2[9][4];
    #pragma unroll
    for (int s = 0; s < 9; s++) {
        gacc2[s][0] = 0ull; gacc2[s][1] = 0ull;
        gacc2[s][2] = 0ull; gacc2[s][3] = 0ull;
    }

    // ---- stage A ----
    const float* wwp = ww_s + wp * 12;
    #pragma unroll 4
    for (int m = 0; m < M_; m++) {
        int nb  = nb_s[m];
        int nbc = (nb == P_) ? 0 : nb;          // ww zeroed for pad
        size_t xo = (size_t)nbc * CI_;
        ull x0 = *(const ull*)(xb[0] + xo);
        ull x1 = *(const ull*)(xb[1] + xo);
        ull x2 = *(const ull*)(xb[2] + xo);
        ull x3 = *(const ull*)(xb[3] + xo);
        const float* wm = wwp + m * WWM;
        float4 fA = *(const float4*)(wm);
        float4 fB = *(const float4*)(wm + 4);
        float  f8 = wm[8];
        float fs[9] = {fA.x, fA.y, fA.z, fA.w, fB.x, fB.y, fB.z, fB.w, f8};
        #pragma unroll
        for (int s = 0; s < 9; s++) {
            ull f2;
            uint32_t fb = __float_as_uint(fs[s]);
            PACK_REPL_F32X2(f2, fb);
            FMA_F32X2(gacc2[s][0], f2, x0, gacc2[s][0]);
            FMA_F32X2(gacc2[s][1], f2, x1, gacc2[s][1]);
            FMA_F32X2(gacc2[s][2], f2, x2, gacc2[s][2]);
            FMA_F32X2(gacc2[s][3], f2, x3, gacc2[s][3]);
        }
    }

    // ---- stage B: XOR-permuted slots; each Wf LDS.64 feeds 4 FFMA2 ----
    const float* wfb = Wf + wp * 16 + 2 * ih;
    const float* biasp = bias + (size_t)p * CO_;
    float* outb = out + ((size_t)b_fin * P_ + p) * CO_;

    #pragma unroll 2
    for (int og = 0; og < 8; og++) {
        float av[4][4];
        float pr[4];

        #pragma unroll
        for (int so = 0; so < 4; so++) {
            const int row = og * 4 + (so ^ oL);
            const float* wfoo = wfb + (size_t)row * OSTRIDE;

            ull acc2[4] = {0ull, 0ull, 0ull, 0ull};
            #pragma unroll
            for (int s = 0; s < 8; s++) {
                ull wv = *(const ull*)(wfoo + s * 32);
                FMA_F32X2(acc2[0], wv, gacc2[s][0], acc2[0]);
                FMA_F32X2(acc2[1], wv, gacc2[s][1], acc2[1]);
                FMA_F32X2(acc2[2], wv, gacc2[s][2], acc2[2]);
                FMA_F32X2(acc2[3], wv, gacc2[s][3], acc2[3]);
            }
            // slot 8: wp0 -> conv w=16 ; wp1 -> wres col * gacc2[8](=0) = 0
            ull wv8 = *(const ull*)(wfoo + 256);
            FMA_F32X2(acc2[0], wv8, gacc2[8][0], acc2[0]);
            FMA_F32X2(acc2[1], wv8, gacc2[8][1], acc2[1]);
            FMA_F32X2(acc2[2], wv8, gacc2[8][2], acc2[2]);
            FMA_F32X2(acc2[3], wv8, gacc2[8][3], acc2[3]);

            #pragma unroll
            for (int sj = 0; sj < 4; sj++) {
                uint32_t lo, hi;
                UNPACK_F32X2(lo, hi, acc2[sj]);
                av[so][sj] = __uint_as_float(lo) + __uint_as_float(hi);
            }

            // residual partial: quarter q = oL of wres row (un-swizzled base!)
            {
                const float* wrow = Wf + (size_t)row * OSTRIDE + 272 + oL * 4;
                ull w2a = *(const ull*)(wrow);
                ull w2b = *(const ull*)(wrow + 2);
                ull t2;
                MUL_F32X2(t2, w2a, xq0);
                FMA_F32X2(t2, w2b, xq1, t2);
                uint32_t lo, hi;
                UNPACK_F32X2(lo, hi, t2);
                pr[so] = __uint_as_float(lo) + __uint_as_float(hi);
            }
        }

        // ---- select-free reduce-scatter (recursive halving, XOR slots) ----
        #pragma unroll
        for (int so = 0; so < 2; so++) {
            #pragma unroll
            for (int sj = 0; sj < 4; sj++)
                av[so][sj] += __shfl_xor_sync(0xffffffffu, av[so + 2][sj], 8);
        }
        // residual ladder: quarters live on (wp,h2) lanes -> xor8 then xor4 only
        pr[0] += __shfl_xor_sync(0xffffffffu, pr[2], 8);
        pr[1] += __shfl_xor_sync(0xffffffffu, pr[3], 8);
        pr[0] += __shfl_xor_sync(0xffffffffu, pr[1], 4);

        #pragma unroll
        for (int sj = 0; sj < 4; sj++)
            av[0][sj] += __shfl_xor_sync(0xffffffffu, av[1][sj], 4);
        #pragma unroll
        for (int sj = 0; sj < 2; sj++)
            av[0][sj] += __shfl_xor_sync(0xffffffffu, av[0][sj + 2], 2);
        av[0][0] += __shfl_xor_sync(0xffffffffu, av[0][1], 1);

        // ---- epilogue: lane owns (o = og*4 + oL, b = b_fin) ----
        const int o = og * 4 + oL;
        float c = av[0][0] + biasp[o];
        float e = (c > 0.0f) ? c : expm1f(c);
        outb[o] = e * SQ_CONV + pr[0] * SQ_RES;
    }
}

extern "C" void kernel_launch(void* const* d_in, const int* in_sizes, int n_in,
                              void* d_out, int out_size)
{
    const float* in_pc       = nullptr;
    const float* weights     = nullptr;
    const float* bias        = nullptr;
    const float* w_weights   = nullptr;
    const float* weight_res  = nullptr;
    const int*   neighbor_id = nullptr;

    for (int i = 0; i < n_in; i++) {
        switch (in_sizes[i]) {
            case 2097152: in_pc       = (const float*)d_in[i]; break; // (8,16384,16)
            case 8704:    weights     = (const float*)d_in[i]; break; // (17,512)
            case 524288:  bias        = (const float*)d_in[i]; break; // (16384,32)
            case 4456448: w_weights   = (const float*)d_in[i]; break; // (16384,16,17)
            case 512:     weight_res  = (const float*)d_in[i]; break; // (32,16)
            case 262144:  neighbor_id = (const int*)d_in[i];   break; // (16384,16)
            default: break;
        }
    }

    const int smem_bytes = (32 * OSTRIDE + 4 * WARP_SM) * 4; // 43264
    cudaFuncSetAttribute(fused_conv_kernel,
                         cudaFuncAttributeMaxDynamicSharedMemorySize, smem_bytes);

    fused_conv_kernel<<<P_ / 4, 128, smem_bytes>>>(
        in_pc, weights, bias, w_weights, weight_res, neighbor_id, (float*)d_out);
}